// round 7
// baseline (speedup 1.0000x reference)
#include <cuda_runtime.h>

#define BB   2
#define NN   512
#define DD   256
#define HH   4
#define HDD  64
#define HDH  256

typedef unsigned long long ull;
#define ABS2 0x7fffffff7fffffffULL

__device__ __align__(16) float g_hq[BB*NN*HDH];
__device__ __align__(16) float g_hk[BB*NN*HDH];
__device__ __align__(16) float g_hv[BB*NN*HDH];

__device__ __forceinline__ ull add2(ull a, ull b) {
    ull r; asm("add.rn.f32x2 %0, %1, %2;" : "=l"(r) : "l"(a), "l"(b)); return r;
}
__device__ __forceinline__ ull fma2(ull a, ull b, ull c) {
    ull r; asm("fma.rn.f32x2 %0, %1, %2, %3;" : "=l"(r) : "l"(a), "l"(b), "l"(c)); return r;
}
__device__ __forceinline__ ull pack2(float lo, float hi) {
    ull r; asm("mov.b64 %0, {%1, %2};" : "=l"(r) : "f"(lo), "f"(hi)); return r;
}
__device__ __forceinline__ float2 unpack2(ull v) {
    float2 f; asm("mov.b64 {%0, %1}, %2;" : "=f"(f.x), "=f"(f.y) : "l"(v)); return f;
}

// ---------------------------------------------------------------------------
// Kernel 1: projections. Tile 16 rows x 128 cols, 256 threads, grid = 384
// (balanced: 2.6 blocks/SM). Thread tile 2x4, scalar FFMA (fma/crossbar
// co-balanced), k-chunk 32, double-buffered with register prefetch.
// ---------------------------------------------------------------------------
__global__ __launch_bounds__(256) void proj_kernel(
    const float* __restrict__ q, const float* __restrict__ k, const float* __restrict__ v,
    const float* __restrict__ wq, const float* __restrict__ bq,
    const float* __restrict__ wv, const float* __restrict__ bv)
{
    __shared__ float sx[2][32][18];    // [buf][k][row] (stride 18: float2-aligned)
    __shared__ float sw[2][32][128];   // [buf][k][col]

    int bid = blockIdx.x;
    int m   = bid >> 7;             // 0=q,1=k,2=v
    int rem = bid & 127;
    int rt  = rem >> 1;             // 64 row tiles of 16
    int ct  = rem & 1;              // 2 col tiles of 128
    int r0 = rt * 16, c0 = ct * 128;

    const float* src  = (m==0) ? q : (m==1) ? k : v;
    const float* W    = (m<2)  ? wq : wv;
    const float* bias = (m<2)  ? bq : bv;
    float* dst        = (m==0) ? g_hq : (m==1) ? g_hk : g_hv;

    int tid = threadIdx.x;
    int ry  = tid >> 5;    // 0..7 -> rows 2ry, 2ry+1
    int cx  = tid & 31;    // cols cx*4..cx*4+3

    float4 b4 = *(const float4*)&bias[c0 + cx*4];
    float4 accA = b4, accB = b4;

    // loader mappings
    int xrow = tid >> 3, xkg = tid & 7;   // threads 0..127: x float4 (16 rows x 8 kgroups)

    // prefetch chunk 0
    float4 xr = make_float4(0.f,0.f,0.f,0.f);
    if (tid < 128) xr = *(const float4*)&src[(size_t)(r0 + xrow)*DD + xkg*4];
    float4 wr[4];
    #pragma unroll
    for (int j = 0; j < 4; j++) {
        int idx = tid + j*256;
        wr[j] = *(const float4*)&W[(size_t)(idx>>5)*DD + c0 + (idx&31)*4];
    }

    if (tid < 128) {
        sx[0][xkg*4+0][xrow] = xr.x;
        sx[0][xkg*4+1][xrow] = xr.y;
        sx[0][xkg*4+2][xrow] = xr.z;
        sx[0][xkg*4+3][xrow] = xr.w;
    }
    #pragma unroll
    for (int j = 0; j < 4; j++) {
        int idx = tid + j*256;
        *(float4*)&sw[0][idx>>5][(idx&31)*4] = wr[j];
    }
    __syncthreads();

    #pragma unroll 1
    for (int c = 0; c < 8; c++) {
        int buf = c & 1;
        if (c < 7) {
            int dbase = (c + 1) * 32;
            if (tid < 128) xr = *(const float4*)&src[(size_t)(r0 + xrow)*DD + dbase + xkg*4];
            #pragma unroll
            for (int j = 0; j < 4; j++) {
                int idx = tid + j*256;
                wr[j] = *(const float4*)&W[(size_t)(dbase + (idx>>5))*DD + c0 + (idx&31)*4];
            }
        }

        #pragma unroll
        for (int kk = 0; kk < 32; kk++) {
            float2 xv = *(const float2*)&sx[buf][kk][2*ry];   // warp broadcast
            float4 wv4 = *(const float4*)&sw[buf][kk][cx*4];  // conflict-free 512B
            accA.x = fmaf(xv.x, wv4.x, accA.x);
            accA.y = fmaf(xv.x, wv4.y, accA.y);
            accA.z = fmaf(xv.x, wv4.z, accA.z);
            accA.w = fmaf(xv.x, wv4.w, accA.w);
            accB.x = fmaf(xv.y, wv4.x, accB.x);
            accB.y = fmaf(xv.y, wv4.y, accB.y);
            accB.z = fmaf(xv.y, wv4.z, accB.z);
            accB.w = fmaf(xv.y, wv4.w, accB.w);
        }

        if (c < 7) {
            int nbuf = buf ^ 1;
            if (tid < 128) {
                sx[nbuf][xkg*4+0][xrow] = xr.x;
                sx[nbuf][xkg*4+1][xrow] = xr.y;
                sx[nbuf][xkg*4+2][xrow] = xr.z;
                sx[nbuf][xkg*4+3][xrow] = xr.w;
            }
            #pragma unroll
            for (int j = 0; j < 4; j++) {
                int idx = tid + j*256;
                *(float4*)&sw[nbuf][idx>>5][(idx&31)*4] = wr[j];
            }
        }
        __syncthreads();
    }

    float4* dst4 = (float4*)dst;
    size_t obase = (size_t)(r0 + 2*ry) * 64 + (c0 >> 2) + cx;
    dst4[obase]      = accA;
    dst4[obase + 64] = accB;
}

// ---------------------------------------------------------------------------
// Kernel 2: main GAT — block per (b,h,16-row i-tile) = 256 blocks, 256 thr,
// 2 blocks/SM. sk/sq computed inline (no base kernel). Register-accumulated
// f-passes. hq/hv streamed in 128-row smem chunks.
// ---------------------------------------------------------------------------
__global__ __launch_bounds__(256, 2) void gat_main(float* __restrict__ out_h,
                                                   float* __restrict__ out_e,
                                                   const float* __restrict__ a_in)
{
    extern __shared__ float sm[];
    float* sh_e  = sm;                    // 16*516
    float* sh_x  = sh_e + 16*516;         // 128*64 (hq chunks, then hv chunks)
    float* sh_hk = sh_x + 128*64;         // 16*68
    float* sh_sq = sh_hk + 16*68;         // 512
    float* sh_p  = sh_sq + 512;           // 16*64
    float* sh_aa = sh_p + 16*64;          // 64
    float* sh_sk = sh_aa + 64;            // 16
    // total 19152 floats = 76608 B

    int bid = blockIdx.x;                 // b(2) * h(4) * it(32)
    int b   = bid >> 7;
    int h   = (bid >> 5) & 3;
    int i0  = (bid & 31) * 16;
    int tid = threadIdx.x;
    int lane = tid & 31;
    int wid  = tid >> 5;

    // stage hk [16 x 64] (stride 68) and aa = 0.4*a
    {
        int r = tid >> 4, fgi = tid & 15;
        float4 kv = ((const float4*)(g_hk + (size_t)(b*NN + i0 + r)*HDH + h*HDD))[fgi];
        *(float4*)&sh_hk[r*68 + fgi*4] = kv;
    }
    if (tid < HDD) sh_aa[tid] = 0.4f * a_in[tid];
    __syncthreads();

    // inline sk: warp w -> rows 2w, 2w+1 ; sk = 1.5 * sum(aa*hk)
    {
        #pragma unroll
        for (int rr = 0; rr < 2; rr++) {
            int r = 2*wid + rr;
            float p = fmaf(sh_aa[lane], sh_hk[r*68 + lane],
                           sh_aa[lane+32] * sh_hk[r*68 + 32 + lane]);
            #pragma unroll
            for (int o = 16; o; o >>= 1) p += __shfl_xor_sync(0xffffffffu, p, o);
            if (lane == 0) sh_sk[r] = 1.5f * p;
        }
    }
    __syncthreads();

    int ii = lane & 15;
    int jh = lane >> 4;
    float sk_i = sh_sk[ii];

    // ---- phase A: logits over 4 hq chunks of 128 rows ----
    #pragma unroll 1
    for (int cs = 0; cs < NN; cs += 128) {
        __syncthreads();
        for (int t = tid; t < 128*16; t += 256) {
            int r = t >> 4, fgi = t & 15;
            ((float4*)sh_x)[t] =
                ((const float4*)(g_hq + (size_t)(b*NN + cs + r)*HDH + h*HDD))[fgi];
        }
        __syncthreads();

        // inline sq for this chunk's rows: warp w -> rows w*16..w*16+15
        {
            #pragma unroll 1
            for (int rr = 0; rr < 16; rr++) {
                int r = wid*16 + rr;
                float p = fmaf(sh_aa[lane], sh_x[r*64 + lane],
                               sh_aa[lane+32] * sh_x[r*64 + 32 + lane]);
                #pragma unroll
                for (int o = 16; o; o >>= 1) p += __shfl_xor_sync(0xffffffffu, p, o);
                if (lane == 0) sh_sq[cs + r] = 1.5f * p;
            }
        }
        __syncthreads();

        float accj[8];
        #pragma unroll 1
        for (int pass = 0; pass < 2; pass++) {
            ull kr[16], aw[16];
            {
                const ulonglong2* kp = (const ulonglong2*)(sh_hk + ii*68 + pass*32);
                const ulonglong2* ap = (const ulonglong2*)(sh_aa + pass*32);
                #pragma unroll
                for (int g = 0; g < 8; g++) {
                    ulonglong2 kk = kp[g];
                    kr[2*g] = kk.x; kr[2*g+1] = kk.y;
                    ulonglong2 av = ap[g];
                    aw[2*g] = av.x; aw[2*g+1] = av.y;
                }
            }
            #pragma unroll 2
            for (int t = 0; t < 8; t++) {
                int jj = wid*16 + t*2 + jh;
                const ulonglong2* q2 = (const ulonglong2*)(sh_x + jj*64 + pass*32);
                ull acc0 = 0ULL, acc1 = 0ULL;
                #pragma unroll
                for (int g = 0; g < 8; g++) {
                    ulonglong2 qq = q2[g];
                    ull t0 = add2(qq.x, kr[2*g]) & ABS2;
                    acc0 = fma2(aw[2*g], t0, acc0);
                    ull t1 = add2(qq.y, kr[2*g+1]) & ABS2;
                    acc1 = fma2(aw[2*g+1], t1, acc1);
                }
                float2 a0 = unpack2(acc0), a1 = unpack2(acc1);
                float s = (a0.x + a0.y) + (a1.x + a1.y);
                if (pass == 0) accj[t] = s;
                else           accj[t] += s;
            }
        }
        #pragma unroll
        for (int t = 0; t < 8; t++) {
            int j = cs + wid*16 + t*2 + jh;
            sh_e[ii*516 + j] = accj[t] + sk_i + sh_sq[j];
        }
    }
    __syncthreads();

    // ---- phase B: row softmax (warp w -> rows 2w, 2w+1) ----
    #pragma unroll
    for (int rr = 0; rr < 2; rr++) {
        float* row = sh_e + (2*wid + rr)*516;
        float mx = -1e30f;
        for (int j = lane; j < NN; j += 32) mx = fmaxf(mx, row[j]);
        #pragma unroll
        for (int o = 16; o; o >>= 1) mx = fmaxf(mx, __shfl_xor_sync(0xffffffffu, mx, o));
        float s = 0.f;
        for (int j = lane; j < NN; j += 32) {
            float ex = __expf(row[j] - mx);
            row[j] = ex;
            s += ex;
        }
        #pragma unroll
        for (int o = 16; o; o >>= 1) s += __shfl_xor_sync(0xffffffffu, s, o);
        float inv = 1.f / s;
        for (int j = lane; j < NN; j += 32) row[j] *= inv;
    }
    __syncthreads();

    // ---- phase C1: write e [B,N,N,H] ----
    {
        float* ebase = out_e + ((size_t)(b*NN + i0) * NN) * HH + h;
        for (int t = tid; t < 16*512; t += 256) {
            int i = t >> 9, j = t & 511;
            ebase[(size_t)(i*NN + j) * HH] = sh_e[i*516 + j];
        }
    }

    // ---- phase C2: AV over 4 hv chunks; warps split j halves; smem reduce ----
    {
        int wq = wid & 3;
        int jhalf = wid >> 2;
        int r0 = 2*wq + (lane >> 4);
        int r1 = r0 + 8;
        int fg = lane & 15;

        ull a00 = 0ULL, a01 = 0ULL, a10 = 0ULL, a11 = 0ULL;

        #pragma unroll 1
        for (int cs = 0; cs < NN; cs += 128) {
            __syncthreads();
            for (int t = tid; t < 128*16; t += 256) {
                int r = t >> 4, fgi = t & 15;
                ((float4*)sh_x)[t] =
                    ((const float4*)(g_hv + (size_t)(b*NN + cs + r)*HDH + h*HDD))[fgi];
            }
            __syncthreads();

            int jb = jhalf * 64;
            #pragma unroll 2
            for (int qv = 0; qv < 64; qv += 4) {
                int jj = jb + qv;
                float4 e0 = *(const float4*)&sh_e[r0*516 + cs + jj];
                float4 e1 = *(const float4*)&sh_e[r1*516 + cs + jj];
                {
                    ulonglong2 vv = *(const ulonglong2*)(sh_x + (jj+0)*64 + fg*4);
                    ull ev0 = pack2(e0.x, e0.x), ev1 = pack2(e1.x, e1.x);
                    a00 = fma2(ev0, vv.x, a00); a01 = fma2(ev0, vv.y, a01);
                    a10 = fma2(ev1, vv.x, a10); a11 = fma2(ev1, vv.y, a11);
                }
                {
                    ulonglong2 vv = *(const ulonglong2*)(sh_x + (jj+1)*64 + fg*4);
                    ull ev0 = pack2(e0.y, e0.y), ev1 = pack2(e1.y, e1.y);
                    a00 = fma2(ev0, vv.x, a00); a01 = fma2(ev0, vv.y, a01);
                    a10 = fma2(ev1, vv.x, a10); a11 = fma2(ev1, vv.y, a11);
                }
                {
                    ulonglong2 vv = *(const ulonglong2*)(sh_x + (jj+2)*64 + fg*4);
                    ull ev0 = pack2(e0.z, e0.z), ev1 = pack2(e1.z, e1.z);
                    a00 = fma2(ev0, vv.x, a00); a01 = fma2(ev0, vv.y, a01);
                    a10 = fma2(ev1, vv.x, a10); a11 = fma2(ev1, vv.y, a11);
                }
                {
                    ulonglong2 vv = *(const ulonglong2*)(sh_x + (jj+3)*64 + fg*4);
                    ull ev0 = pack2(e0.w, e0.w), ev1 = pack2(e1.w, e1.w);
                    a00 = fma2(ev0, vv.x, a00); a01 = fma2(ev0, vv.y, a01);
                    a10 = fma2(ev1, vv.x, a10); a11 = fma2(ev1, vv.y, a11);
                }
            }
        }
        __syncthreads();
        if (jhalf == 1) {
            *(ulonglong2*)&sh_p[r0*64 + fg*4] = make_ulonglong2(a00, a01);
            *(ulonglong2*)&sh_p[r1*64 + fg*4] = make_ulonglong2(a10, a11);
        }
        __syncthreads();
        if (jhalf == 0) {
            ulonglong2 p0 = *(const ulonglong2*)&sh_p[r0*64 + fg*4];
            ulonglong2 p1 = *(const ulonglong2*)&sh_p[r1*64 + fg*4];
            a00 = add2(a00, p0.x); a01 = add2(a01, p0.y);
            a10 = add2(a10, p1.x); a11 = add2(a11, p1.y);
            float2 f0 = unpack2(a00), f1 = unpack2(a01);
            float2 f2 = unpack2(a10), f3 = unpack2(a11);
            float4 ra = make_float4(fmaxf(f0.x,0.f), fmaxf(f0.y,0.f),
                                    fmaxf(f1.x,0.f), fmaxf(f1.y,0.f));
            float4 rb = make_float4(fmaxf(f2.x,0.f), fmaxf(f2.y,0.f),
                                    fmaxf(f3.x,0.f), fmaxf(f3.y,0.f));
            *(float4*)&out_h[(size_t)(b*NN + i0 + r0)*HDH + h*HDD + fg*4] = ra;
            *(float4*)&out_h[(size_t)(b*NN + i0 + r1)*HDH + h*HDD + fg*4] = rb;
        }
    }
}

// ---------------------------------------------------------------------------
extern "C" void kernel_launch(void* const* d_in, const int* in_sizes, int n_in,
                              void* d_out, int out_size)
{
    const float* q  = (const float*)d_in[0];
    const float* k  = (const float*)d_in[1];
    const float* v  = (const float*)d_in[2];
    const float* wq = (const float*)d_in[3];
    const float* bq = (const float*)d_in[4];
    const float* wv = (const float*)d_in[5];
    const float* bv = (const float*)d_in[6];
    const float* a  = (const float*)d_in[7];

    float* out_h = (float*)d_out;
    float* out_e = out_h + (size_t)BB*NN*HDH;

    const int smem_main = (16*516 + 128*64 + 16*68 + 512 + 16*64 + 64 + 16) * (int)sizeof(float);
    cudaFuncSetAttribute(gat_main, cudaFuncAttributeMaxDynamicSharedMemorySize, smem_main);

    proj_kernel<<<384, 256>>>(q, k, v, wq, bq, wv, bv);
    gat_main<<<256, 256, smem_main>>>(out_h, out_e, a);
}